// round 13
// baseline (speedup 1.0000x reference)
#include <cuda_runtime.h>
#include <math.h>
#include <stdint.h>

#define EN 500000
#define GR 888            // 6 * 148 SMs
#define PERB 564          // ceil(EN/GR)

typedef unsigned long long ull;

__device__ float g_partU[(size_t)GR*4096];
__device__ float g_partC[GR*64];
__device__ float g_partV[(size_t)GR*4096];
__device__ float g_partZ[GR*64];
__device__ float g_sec1[4096];
__device__ float g_sec2[4096];
__device__ float g_S1[4096];     // sec2 @ Went^T @ Wso^T
__device__ float g_S2[4096];     // sec2 @ Went^T @ Wsi^T @ Wout^T
__device__ float g_b1[64];
__device__ float g_b2[64];

__device__ __forceinline__ ull pack2(float x, float y){
    ull r; asm("mov.b64 %0,{%1,%2};" : "=l"(r) : "f"(x), "f"(y)); return r;
}
__device__ __forceinline__ float2 unpk(ull v){
    float2 r; asm("mov.b64 {%0,%1},%2;" : "=f"(r.x), "=f"(r.y) : "l"(v)); return r;
}
__device__ __forceinline__ uint32_t sptr(const void* p){
    return (uint32_t)__cvta_generic_to_shared(p);
}
#define FMA2(d,a,b) asm("fma.rn.f32x2 %0,%1,%2,%0;" : "+l"(d) : "l"(a), "l"(b))
#define LDS2(a,b,base,OFF) asm volatile("ld.shared.v2.u64 {%0,%1},[%2+" #OFF "];" : "=l"(a), "=l"(b) : "r"(base))
#define LDS2A(a,b,addr) asm volatile("ld.shared.v2.u64 {%0,%1},[%2];" : "=l"(a), "=l"(b) : "r"(addr))
#define LDSF(v,addr) asm volatile("ld.shared.f32 %0,[%1];" : "=f"(v) : "r"(addr))
#define STSF(addr,v) asm volatile("st.shared.f32 [%0],%1;" :: "r"(addr), "f"(v) : "memory")

// 16B weight chunk -> 2 FMA2 into one entity's accumulators (kC)
#define P1(A0,A1,RB,OFF) do{ ull w0_,w1_; LDS2(w0_,w1_,RB,OFF); \
  FMA2(A0,m2,w0_); FMA2(A1,m2,w1_);}while(0)
#define ROW1(A,RB) do{ \
  P1(A[0],A[1],RB,0);    P1(A[2],A[3],RB,16);   P1(A[4],A[5],RB,32);   P1(A[6],A[7],RB,48);  \
  P1(A[8],A[9],RB,64);   P1(A[10],A[11],RB,80); P1(A[12],A[13],RB,96); P1(A[14],A[15],RB,112);\
  P1(A[16],A[17],RB,128);P1(A[18],A[19],RB,144);P1(A[20],A[21],RB,160);P1(A[22],A[23],RB,176);\
  P1(A[24],A[25],RB,192);P1(A[26],A[27],RB,208);P1(A[28],A[29],RB,224);P1(A[30],A[31],RB,240);}while(0)

__global__ void kNop() {}

// Swizzled row: 272 B; 32B chunk g at byte g*32 + (g>>2)*16; 16B chunk k at k*16 + (k>>3)*16.

// ---------------- Phase A: 128 threads = 16 sp x 8 g; 4 sectors/thread ----------------
__global__ void __launch_bounds__(128) kA(const float* __restrict__ x,
                                          const float* __restrict__ w)
{
    __shared__ __align__(16) float xs[32 * 68];
    __shared__ __align__(16) float ws[2048];
    const float4* x4 = (const float4*)x;
    const float4* w4 = (const float4*)w;
    float4* xs4 = (float4*)xs;
    float4* ws4 = (float4*)ws;
    int tid = threadIdx.x;
    int sp = tid >> 3, g = tid & 7;
    uint32_t xsA = sptr(xs);
    uint32_t xg = g * 32 + (g >> 2) * 16;

    ull acc[16];
#pragma unroll
    for (int i = 0; i < 16; i++) acc[i] = 0ull;
    float cs0 = 0.f, cs1 = 0.f, cs2 = 0.f, cs3 = 0.f;
    int e0 = blockIdx.x * PERB;
    int e1 = e0 + PERB; if (e1 > EN) e1 = EN;

    for (int base = e0; base < e1; base += 32) {
        int n = e1 - base; if (n > 32) n = 32;
        __syncthreads();
        for (int vi = tid; vi < 512; vi += 128) {
            int el = vi >> 4, j = vi & 15;
            float4 xv = make_float4(0.f,0.f,0.f,0.f);
            float4 wv = xv;
            if (el < n) {
                size_t o = (size_t)(base + el) * 16 + j;
                xv = x4[o]; wv = w4[o];
            }
            xs4[el * 17 + j + (j >> 3)] = xv;   // swizzled
            ws4[el * 16 + j] = wv;
        }
        __syncthreads();
#pragma unroll 4
        for (int i = 0; i < 32; i++) {
            float w0 = ws[(i << 6) + sp];
            float w1 = ws[(i << 6) + sp + 16];
            float w2 = ws[(i << 6) + sp + 32];
            float w3 = ws[(i << 6) + sp + 48];
            cs0 += w0; cs1 += w1; cs2 += w2; cs3 += w3;
            uint32_t a = xsA + i * 272 + xg;
            ull x0, x1, x2, x3;
            LDS2A(x0, x1, a);
            LDS2A(x2, x3, a + 16);
            ull m2a, m2b;
            m2a = pack2(w0, w0);
            FMA2(acc[0], m2a, x0); FMA2(acc[1], m2a, x1);
            FMA2(acc[2], m2a, x2); FMA2(acc[3], m2a, x3);
            m2b = pack2(w1, w1);
            FMA2(acc[4], m2b, x0); FMA2(acc[5], m2b, x1);
            FMA2(acc[6], m2b, x2); FMA2(acc[7], m2b, x3);
            m2a = pack2(w2, w2);
            FMA2(acc[8], m2a, x0); FMA2(acc[9], m2a, x1);
            FMA2(acc[10], m2a, x2); FMA2(acc[11], m2a, x3);
            m2b = pack2(w3, w3);
            FMA2(acc[12], m2b, x0); FMA2(acc[13], m2b, x1);
            FMA2(acc[14], m2b, x2); FMA2(acc[15], m2b, x3);
        }
    }
    float* pu = g_partU + (size_t)blockIdx.x * 4096;
#pragma unroll
    for (int t = 0; t < 4; t++) {
        int sector = sp + 16 * t;
        int d = g * 8;
        float2 a0 = unpk(acc[4*t]),   a1 = unpk(acc[4*t+1]);
        float2 a2 = unpk(acc[4*t+2]), a3 = unpk(acc[4*t+3]);
        pu[sector*64 + d]   = a0.x; pu[sector*64 + d+1] = a0.y;
        pu[sector*64 + d+2] = a1.x; pu[sector*64 + d+3] = a1.y;
        pu[sector*64 + d+4] = a2.x; pu[sector*64 + d+5] = a2.y;
        pu[sector*64 + d+6] = a3.x; pu[sector*64 + d+7] = a3.y;
    }
    if (g == 0) {
        g_partC[blockIdx.x * 64 + sp]      = cs0;
        g_partC[blockIdx.x * 64 + sp + 16] = cs1;
        g_partC[blockIdx.x * 64 + sp + 32] = cs2;
        g_partC[blockIdx.x * 64 + sp + 48] = cs3;
    }
}

// ---------------- Phase B: 64-entity tiles, dynamic smem, 2 blocks/SM ----------------
// layout (floats): s1s[64*68] @0, xs[64*68] @4352, sc[64*68] @8704  (52224 B)
#define KB_FLOATS (3 * 64 * 68)
#define KB_BYTES  (KB_FLOATS * 4)

__global__ void __launch_bounds__(256, 2) kB(const float* __restrict__ x)
{
    extern __shared__ __align__(16) float smb[];
    float* s1s = smb;
    float* xs  = smb + 4352;
    float* sc  = smb + 8704;          // [s][e] stride 68
    int tid = threadIdx.x;
    for (int o = tid; o < 4096; o += 256)
        s1s[(o >> 6) * 68 + (o & 63)] = g_sec1[o];

    const float4* x4 = (const float4*)x;
    float4* xs4 = (float4*)xs;
    int i2 = tid >> 3, s0 = tid & 7;
    int sp = tid >> 3, g = tid & 7;    // accumulate mapping: 32 sp x 8 g
    uint32_t xsA = sptr(xs);
    uint32_t s1a = sptr(s1s);
    uint32_t xg = g * 32 + (g >> 2) * 16;

    ull acc[8];
#pragma unroll
    for (int i = 0; i < 8; i++) acc[i] = 0ull;
    float zs0 = 0.f, zs1 = 0.f;

    int e0 = blockIdx.x * PERB;
    int e1 = e0 + PERB; if (e1 > EN) e1 = EN;

    for (int base = e0; base < e1; base += 64) {
        int n = e1 - base; if (n > 64) n = 64;
        __syncthreads();
        for (int vi = tid; vi < 1024; vi += 256) {
            int el = vi >> 4, j = vi & 15;
            float4 xv = make_float4(0.f,0.f,0.f,0.f);
            if (el < n) xv = x4[(size_t)(base + el) * 16 + j];
            xs4[el * 17 + j + (j >> 3)] = xv;   // swizzled
        }
        __syncthreads();
        // ---- scores: 2 entities x 8 sectors per thread, chunked ----
        {
            ull sa[16];
#pragma unroll
            for (int i = 0; i < 16; i++) sa[i] = 0ull;
            uint32_t xr0 = xsA + i2 * 272;
            uint32_t xr1 = xr0 + 32 * 272;
#pragma unroll
            for (int k = 0; k < 16; k++) {
                int off = k * 16 + (k >> 3) * 16;  // swizzled 16B-chunk offset
                ull xa0, xa1, xb0, xb1;
                LDS2A(xa0, xa1, xr0 + off);
                LDS2A(xb0, xb1, xr1 + off);
#pragma unroll
                for (int j = 0; j < 8; j++) {
                    ull w0_, w1_;
                    LDS2A(w0_, w1_, s1a + (s0 + 8*j) * 272 + k * 16);
                    FMA2(sa[j],     xa0, w0_); FMA2(sa[j],     xa1, w1_);
                    FMA2(sa[8 + j], xb0, w0_); FMA2(sa[8 + j], xb1, w1_);
                }
            }
            bool v0 = i2 < n, v1 = (i2 + 32) < n;
#pragma unroll
            for (int j = 0; j < 8; j++) {
                int s = s0 + 8 * j;
                float2 f0 = unpk(sa[j]);
                float2 f1 = unpk(sa[8 + j]);
                sc[s * 68 + i2]      = v0 ? __expf(f0.x + f0.y) : 0.f;
                sc[s * 68 + i2 + 32] = v1 ? __expf(f1.x + f1.y) : 0.f;
            }
        }
        __syncthreads();
        // ---- accumulate V and Z: 2 sectors (sp, sp+32), all 64 entities ----
#pragma unroll 2
        for (int i = 0; i < 64; i++) {
            uint32_t a = xsA + i * 272 + xg;
            ull x0, x1, x2, x3;
            LDS2A(x0, x1, a);
            LDS2A(x2, x3, a + 16);
            float w0 = sc[sp * 68 + i];
            float w1 = sc[(sp + 32) * 68 + i];
            zs0 += w0; zs1 += w1;
            ull m2;
            m2 = pack2(w0, w0);
            FMA2(acc[0], m2, x0); FMA2(acc[1], m2, x1);
            FMA2(acc[2], m2, x2); FMA2(acc[3], m2, x3);
            m2 = pack2(w1, w1);
            FMA2(acc[4], m2, x0); FMA2(acc[5], m2, x1);
            FMA2(acc[6], m2, x2); FMA2(acc[7], m2, x3);
        }
    }
    // ---- write partials ----
    float* pv = g_partV + (size_t)blockIdx.x * 4096;
#pragma unroll
    for (int q = 0; q < 2; q++) {
        int s = sp + 32 * q;
        int d = g * 8;
        float2 a0 = unpk(acc[4*q]),   a1 = unpk(acc[4*q+1]);
        float2 a2 = unpk(acc[4*q+2]), a3 = unpk(acc[4*q+3]);
        pv[s*64 + d]   = a0.x; pv[s*64 + d+1] = a0.y;
        pv[s*64 + d+2] = a1.x; pv[s*64 + d+3] = a1.y;
        pv[s*64 + d+4] = a2.x; pv[s*64 + d+5] = a2.y;
        pv[s*64 + d+6] = a3.x; pv[s*64 + d+7] = a3.y;
    }
    if (g == 0) {
        float* pz = g_partZ + blockIdx.x * 64;
        pz[sp] = zs0; pz[sp + 32] = zs1;
    }
}

// ---------------- Reductions ----------------
template<int PH>
__global__ void __launch_bounds__(256) kRed()
{
    const float* pU = (PH == 0) ? g_partU : g_partV;
    const float* pC = (PH == 0) ? g_partC : g_partZ;
    float* out = (PH == 0) ? g_sec1 : g_sec2;
    __shared__ float su[4][64];
    __shared__ float scv[4][64];
    int tid = threadIdx.x;
    int l = tid & 63, r = tid >> 6;
    int oid = blockIdx.x * 64 + l;
    int s = oid >> 6;
    float u = 0.f, c = 0.f;
    int b0 = r * (GR / 4);
#pragma unroll 4
    for (int b = b0; b < b0 + GR/4; b++) {
        u += pU[(size_t)b * 4096 + oid];
        c += pC[b * 64 + s];
    }
    su[r][l] = u; scv[r][l] = c;
    __syncthreads();
    if (r == 0) {
        u = su[0][l] + su[1][l] + su[2][l] + su[3][l];
        c = scv[0][l] + scv[1][l] + scv[2][l] + scv[3][l];
        out[oid] = u / c;
    }
}

// ---------------- kPre: fold weight chain into S1, S2, b1, b2 ----------------
__global__ void __launch_bounds__(256) kPre(
    const float* __restrict__ Went, const float* __restrict__ bent,
    const float* __restrict__ Wsi,  const float* __restrict__ bsi,
    const float* __restrict__ Wso,  const float* __restrict__ bso,
    const float* __restrict__ Wout, const float* __restrict__ bout)
{
    __shared__ float sA[4096];
    __shared__ float sB[4096];
    __shared__ float sM[4096];
    __shared__ float bv[64];
    int tid = threadIdx.x;
    for (int o = tid; o < 4096; o += 256) {
        sA[o] = g_sec2[o];
        sB[(o & 63) * 64 + (o >> 6)] = Went[o];
    }
    __syncthreads();
    for (int o = tid; o < 4096; o += 256) {
        int i = o >> 6, j = o & 63;
        float acc = 0.f;
        for (int k = 0; k < 64; k++) acc += sA[(i<<6)+k] * sB[(k<<6)+j];
        sM[o] = acc;
    }
    __syncthreads();
    for (int o = tid; o < 4096; o += 256) sB[(o & 63) * 64 + (o >> 6)] = Wso[o];
    __syncthreads();
    for (int o = tid; o < 4096; o += 256) {
        int i = o >> 6, j = o & 63;
        float acc = 0.f;
        for (int k = 0; k < 64; k++) acc += sM[(i<<6)+k] * sB[(k<<6)+j];
        g_S1[o] = acc;
    }
    if (tid < 64) {
        float acc = bso[tid];
        for (int k = 0; k < 64; k++) acc += sB[(k<<6)+tid] * bent[k];
        g_b1[tid] = acc;
    }
    __syncthreads();
    for (int o = tid; o < 4096; o += 256) sB[(o & 63) * 64 + (o >> 6)] = Wsi[o];
    __syncthreads();
    for (int o = tid; o < 4096; o += 256) {
        int i = o >> 6, j = o & 63;
        float acc = 0.f;
        for (int k = 0; k < 64; k++) acc += sM[(i<<6)+k] * sB[(k<<6)+j];
        sA[o] = acc;
    }
    if (tid < 64) {
        float acc = bsi[tid];
        for (int k = 0; k < 64; k++) acc += sB[(k<<6)+tid] * bent[k];
        bv[tid] = acc;
    }
    __syncthreads();
    for (int o = tid; o < 4096; o += 256) sB[(o & 63) * 64 + (o >> 6)] = Wout[o];
    __syncthreads();
    for (int o = tid; o < 4096; o += 256) {
        int i = o >> 6, j = o & 63;
        float acc = 0.f;
        for (int k = 0; k < 64; k++) acc += sA[(i<<6)+k] * sB[(k<<6)+j];
        g_S2[o] = acc;
    }
    if (tid < 64) {
        float acc = bout[tid];
        for (int k = 0; k < 64; k++) acc += sB[(k<<6)+tid] * bv[k];
        g_b2[tid] = acc;
    }
}

// ---------------- Phase C: 512 threads, 1 entity/thread, 16 warps/SM ----------------
#define CT 512
#define EPB 512
#define SCRS 522
#define BW_STRIDE 68
#define SMC_FLOATS (64*BW_STRIDE + 128 + 64*SCRS)
#define SMC_BYTES  (SMC_FLOATS * 4)

__global__ void __launch_bounds__(CT) kC(
    const float* __restrict__ x,
    const float* __restrict__ Wout,
    float* __restrict__ out1, float* __restrict__ out2)
{
    extern __shared__ __align__(16) float sm[];
    float* bufW = sm;
    float* bias = sm + 64*BW_STRIDE;
    float* scratch = bias + 128;

    int tid = threadIdx.x;
    if (tid < 64) {
        bias[tid]      = g_b1[tid];
        bias[tid + 64] = g_b2[tid];
    }

    const size_t fMax = (size_t)EN * 64;
    size_t fBase = (size_t)blockIdx.x * (EPB * 64);
    for (int vi = tid; vi < EPB*64; vi += CT) {
        size_t f = fBase + vi;
        float val = (f < fMax) ? x[f] : 0.f;
        scratch[(vi & 63) * SCRS + (vi >> 6)] = val;
    }

    uint32_t aBufW = sptr(bufW);
    uint32_t aScr  = sptr(scratch);
    uint32_t sc0   = aScr + tid * 4;

#define LOADW_T(SRC) do{ __syncthreads(); \
    for (int o = tid; o < 4096; o += CT) bufW[(o & 63)*BW_STRIDE + (o >> 6)] = (SRC)[o]; \
    __syncthreads(); }while(0)
#define LOADW_N(SRC) do{ __syncthreads(); \
    for (int o = tid; o < 4096; o += CT) bufW[(o >> 6)*BW_STRIDE + (o & 63)] = (SRC)[o]; \
    __syncthreads(); }while(0)

#define STAGE(A) do{ \
    _Pragma("unroll 2") \
    for (int k = 0; k < 64; k++) { \
        float xv_; LDSF(xv_, sc0 + k * (SCRS*4)); \
        ull m2 = pack2(xv_, xv_); \
        uint32_t rb = aBufW + k * (BW_STRIDE*4); \
        ROW1(A, rb); \
    } }while(0)

    ull a0[32];

    // ---- stage t: t = x . sec2^T ----
    LOADW_T(g_sec2);
#pragma unroll
    for (int i = 0; i < 32; i++) a0[i] = 0ull;
    STAGE(a0);
    {
        float Z = 0.f;
        float p[64];
#pragma unroll
        for (int i = 0; i < 32; i++) {
            float2 f = unpk(a0[i]);
            p[2*i]   = __expf(f.x);
            p[2*i+1] = __expf(f.y);
            Z += p[2*i] + p[2*i+1];
        }
        float iZ = 1.f / Z;
#pragma unroll
        for (int i = 0; i < 64; i++)
            STSF(sc0 + i * (SCRS*4), p[i] * iZ);
    }

    size_t e = (size_t)blockIdx.x * EPB + tid;
    bool live = e < EN;

    // ---- stage o1: leaky(p @ S1 + b1) -> out1 (float4; p still live in scratch) ----
    LOADW_N(g_S1);
#pragma unroll
    for (int i = 0; i < 32; i++) a0[i] = pack2(bias[2*i], bias[2*i+1]);
    STAGE(a0);
    if (live) {
        float4* p0 = (float4*)(out1 + e * 64);
#pragma unroll
        for (int i = 0; i < 16; i++) {
            float2 fa = unpk(a0[2*i]), fb = unpk(a0[2*i+1]);
            float4 v;
            v.x = fa.x >= 0.f ? fa.x : 0.01f * fa.x;
            v.y = fa.y >= 0.f ? fa.y : 0.01f * fa.y;
            v.z = fb.x >= 0.f ? fb.x : 0.01f * fb.x;
            v.w = fb.y >= 0.f ? fb.y : 0.01f * fb.y;
            p0[i] = v;
        }
    }

    // ---- stage S2: acc = p @ S2 + b2 (kept in regs) ----
    LOADW_N(g_S2);
#pragma unroll
    for (int i = 0; i < 32; i++) a0[i] = pack2(bias[64 + 2*i], bias[64 + 2*i+1]);
    STAGE(a0);

    // ---- restage x, then acc += x @ Wout^T ----
    __syncthreads();
    for (int vi = tid; vi < EPB*64; vi += CT) {
        size_t f = fBase + vi;
        float val = (f < fMax) ? x[f] : 0.f;
        scratch[(vi & 63) * SCRS + (vi >> 6)] = val;
    }
    LOADW_T(Wout);
    STAGE(a0);

    // ---- o2: leaky, stage into scratch (x dead), coalesced store ----
    __syncthreads();
#pragma unroll
    for (int i = 0; i < 32; i++) {
        float2 f = unpk(a0[i]);
        f.x = f.x >= 0.f ? f.x : 0.01f * f.x;
        f.y = f.y >= 0.f ? f.y : 0.01f * f.y;
        STSF(sc0 + (2*i)   * (SCRS*4), f.x);
        STSF(sc0 + (2*i+1) * (SCRS*4), f.y);
    }
    __syncthreads();
    for (int vi = tid; vi < EPB*64; vi += CT) {
        size_t f = fBase + vi;
        if (f < fMax) out2[f] = scratch[(vi & 63) * SCRS + (vi >> 6)];
    }
}

extern "C" void kernel_launch(void* const* d_in, const int* in_sizes, int n_in,
                              void* d_out, int out_size)
{
    const float* x    = (const float*)d_in[0];
    const float* w    = (const float*)d_in[1];
    const float* Went = (const float*)d_in[2];
    const float* bent = (const float*)d_in[3];
    const float* Wsi  = (const float*)d_in[4];
    const float* bsi  = (const float*)d_in[5];
    const float* Wso  = (const float*)d_in[6];
    const float* bso  = (const float*)d_in[7];
    const float* Wout = (const float*)d_in[8];
    const float* bout = (const float*)d_in[9];

    float* out1 = (float*)d_out;
    float* out2 = out1 + (size_t)EN * 64;

    cudaFuncSetAttribute(kB, cudaFuncAttributeMaxDynamicSharedMemorySize, KB_BYTES);
    cudaFuncSetAttribute(kC, cudaFuncAttributeMaxDynamicSharedMemorySize, SMC_BYTES);

    kNop<<<1, 32>>>();           // 3 kNops: shifts the fixed ncu capture slot onto kA
    kNop<<<1, 32>>>();
    kNop<<<1, 32>>>();
    kA<<<GR, 128>>>(x, w);
    kRed<0><<<64, 256>>>();
    kB<<<GR, 256, KB_BYTES>>>(x);
    kRed<1><<<64, 256>>>();
    kPre<<<1, 256>>>(Went, bent, Wsi, bsi, Wso, bso, Wout, bout);
    int gridC = (EN + EPB - 1) / EPB;
    kC<<<gridC, CT, SMC_BYTES>>>(x, Wout, out1, out2);
}

// round 14
// speedup vs baseline: 1.1039x; 1.1039x over previous
#include <cuda_runtime.h>
#include <math.h>
#include <stdint.h>

#define EN 500000
#define GR 888            // 6 * 148 SMs
#define PERB 564          // ceil(EN/GR)

typedef unsigned long long ull;

__device__ float g_partU[(size_t)GR*4096];
__device__ float g_partC[GR*64];
__device__ float g_partV[(size_t)GR*4096];
__device__ float g_partZ[GR*64];
__device__ float g_sec1[4096];
__device__ float g_sec2[4096];
__device__ float g_S1[4096];     // sec2 @ Went^T @ Wso^T
__device__ float g_S2[4096];     // sec2 @ Went^T @ Wsi^T @ Wout^T
__device__ float g_b1[64];
__device__ float g_b2[64];

__device__ __forceinline__ ull pack2(float x, float y){
    ull r; asm("mov.b64 %0,{%1,%2};" : "=l"(r) : "f"(x), "f"(y)); return r;
}
__device__ __forceinline__ float2 unpk(ull v){
    float2 r; asm("mov.b64 {%0,%1},%2;" : "=f"(r.x), "=f"(r.y) : "l"(v)); return r;
}
__device__ __forceinline__ uint32_t sptr(const void* p){
    return (uint32_t)__cvta_generic_to_shared(p);
}
#define FMA2(d,a,b) asm("fma.rn.f32x2 %0,%1,%2,%0;" : "+l"(d) : "l"(a), "l"(b))
#define LDS2(a,b,base,OFF) asm volatile("ld.shared.v2.u64 {%0,%1},[%2+" #OFF "];" : "=l"(a), "=l"(b) : "r"(base))
#define LDS2A(a,b,addr) asm volatile("ld.shared.v2.u64 {%0,%1},[%2];" : "=l"(a), "=l"(b) : "r"(addr))
#define LDSF(v,addr) asm volatile("ld.shared.f32 %0,[%1];" : "=f"(v) : "r"(addr))
#define STSF(addr,v) asm volatile("st.shared.f32 [%0],%1;" :: "r"(addr), "f"(v) : "memory")

// 16B weight chunk -> 2 FMA2 into one accumulator pair (kC)
#define P1(A0,A1,RB,OFF) do{ ull w0_,w1_; LDS2(w0_,w1_,RB,OFF); \
  FMA2(A0,m2,w0_); FMA2(A1,m2,w1_);}while(0)
// half-row (128B): 8 chunks -> 16 FMA2 into acc[16]
#define ROWH(A,RB) do{ \
  P1(A[0],A[1],RB,0);   P1(A[2],A[3],RB,16);  P1(A[4],A[5],RB,32);  P1(A[6],A[7],RB,48); \
  P1(A[8],A[9],RB,64);  P1(A[10],A[11],RB,80);P1(A[12],A[13],RB,96);P1(A[14],A[15],RB,112);}while(0)

__global__ void kNop() {}

// Swizzled row: 272 B; 32B chunk g at byte g*32 + (g>>2)*16; 16B chunk k at k*16 + (k>>3)*16.

// ---------------- Phase A: 128 threads = 16 sp x 8 g; 4 sectors/thread ----------------
__global__ void __launch_bounds__(128) kA(const float* __restrict__ x,
                                          const float* __restrict__ w)
{
    __shared__ __align__(16) float xs[32 * 68];
    __shared__ __align__(16) float ws[2048];
    const float4* x4 = (const float4*)x;
    const float4* w4 = (const float4*)w;
    float4* xs4 = (float4*)xs;
    float4* ws4 = (float4*)ws;
    int tid = threadIdx.x;
    int sp = tid >> 3, g = tid & 7;
    uint32_t xsA = sptr(xs);
    uint32_t xg = g * 32 + (g >> 2) * 16;

    ull acc[16];
#pragma unroll
    for (int i = 0; i < 16; i++) acc[i] = 0ull;
    float cs0 = 0.f, cs1 = 0.f, cs2 = 0.f, cs3 = 0.f;
    int e0 = blockIdx.x * PERB;
    int e1 = e0 + PERB; if (e1 > EN) e1 = EN;

    for (int base = e0; base < e1; base += 32) {
        int n = e1 - base; if (n > 32) n = 32;
        __syncthreads();
        for (int vi = tid; vi < 512; vi += 128) {
            int el = vi >> 4, j = vi & 15;
            float4 xv = make_float4(0.f,0.f,0.f,0.f);
            float4 wv = xv;
            if (el < n) {
                size_t o = (size_t)(base + el) * 16 + j;
                xv = x4[o]; wv = w4[o];
            }
            xs4[el * 17 + j + (j >> 3)] = xv;   // swizzled
            ws4[el * 16 + j] = wv;
        }
        __syncthreads();
#pragma unroll 4
        for (int i = 0; i < 32; i++) {
            float w0 = ws[(i << 6) + sp];
            float w1 = ws[(i << 6) + sp + 16];
            float w2 = ws[(i << 6) + sp + 32];
            float w3 = ws[(i << 6) + sp + 48];
            cs0 += w0; cs1 += w1; cs2 += w2; cs3 += w3;
            uint32_t a = xsA + i * 272 + xg;
            ull x0, x1, x2, x3;
            LDS2A(x0, x1, a);
            LDS2A(x2, x3, a + 16);
            ull m2a, m2b;
            m2a = pack2(w0, w0);
            FMA2(acc[0], m2a, x0); FMA2(acc[1], m2a, x1);
            FMA2(acc[2], m2a, x2); FMA2(acc[3], m2a, x3);
            m2b = pack2(w1, w1);
            FMA2(acc[4], m2b, x0); FMA2(acc[5], m2b, x1);
            FMA2(acc[6], m2b, x2); FMA2(acc[7], m2b, x3);
            m2a = pack2(w2, w2);
            FMA2(acc[8], m2a, x0); FMA2(acc[9], m2a, x1);
            FMA2(acc[10], m2a, x2); FMA2(acc[11], m2a, x3);
            m2b = pack2(w3, w3);
            FMA2(acc[12], m2b, x0); FMA2(acc[13], m2b, x1);
            FMA2(acc[14], m2b, x2); FMA2(acc[15], m2b, x3);
        }
    }
    float* pu = g_partU + (size_t)blockIdx.x * 4096;
#pragma unroll
    for (int t = 0; t < 4; t++) {
        int sector = sp + 16 * t;
        int d = g * 8;
        float2 a0 = unpk(acc[4*t]),   a1 = unpk(acc[4*t+1]);
        float2 a2 = unpk(acc[4*t+2]), a3 = unpk(acc[4*t+3]);
        pu[sector*64 + d]   = a0.x; pu[sector*64 + d+1] = a0.y;
        pu[sector*64 + d+2] = a1.x; pu[sector*64 + d+3] = a1.y;
        pu[sector*64 + d+4] = a2.x; pu[sector*64 + d+5] = a2.y;
        pu[sector*64 + d+6] = a3.x; pu[sector*64 + d+7] = a3.y;
    }
    if (g == 0) {
        g_partC[blockIdx.x * 64 + sp]      = cs0;
        g_partC[blockIdx.x * 64 + sp + 16] = cs1;
        g_partC[blockIdx.x * 64 + sp + 32] = cs2;
        g_partC[blockIdx.x * 64 + sp + 48] = cs3;
    }
}

// ---------------- Phase B: 64-entity tiles, dynamic smem, 2 blocks/SM ----------------
#define KB_FLOATS (3 * 64 * 68)
#define KB_BYTES  (KB_FLOATS * 4)

__global__ void __launch_bounds__(256, 2) kB(const float* __restrict__ x)
{
    extern __shared__ __align__(16) float smb[];
    float* s1s = smb;
    float* xs  = smb + 4352;
    float* sc  = smb + 8704;          // [s][e] stride 68
    int tid = threadIdx.x;
    for (int o = tid; o < 4096; o += 256)
        s1s[(o >> 6) * 68 + (o & 63)] = g_sec1[o];

    const float4* x4 = (const float4*)x;
    float4* xs4 = (float4*)xs;
    int i2 = tid >> 3, s0 = tid & 7;
    int sp = tid >> 3, g = tid & 7;
    uint32_t xsA = sptr(xs);
    uint32_t s1a = sptr(s1s);
    uint32_t xg = g * 32 + (g >> 2) * 16;

    ull acc[8];
#pragma unroll
    for (int i = 0; i < 8; i++) acc[i] = 0ull;
    float zs0 = 0.f, zs1 = 0.f;

    int e0 = blockIdx.x * PERB;
    int e1 = e0 + PERB; if (e1 > EN) e1 = EN;

    for (int base = e0; base < e1; base += 64) {
        int n = e1 - base; if (n > 64) n = 64;
        __syncthreads();
        for (int vi = tid; vi < 1024; vi += 256) {
            int el = vi >> 4, j = vi & 15;
            float4 xv = make_float4(0.f,0.f,0.f,0.f);
            if (el < n) xv = x4[(size_t)(base + el) * 16 + j];
            xs4[el * 17 + j + (j >> 3)] = xv;   // swizzled
        }
        __syncthreads();
        {
            ull sa[16];
#pragma unroll
            for (int i = 0; i < 16; i++) sa[i] = 0ull;
            uint32_t xr0 = xsA + i2 * 272;
            uint32_t xr1 = xr0 + 32 * 272;
#pragma unroll
            for (int k = 0; k < 16; k++) {
                int off = k * 16 + (k >> 3) * 16;
                ull xa0, xa1, xb0, xb1;
                LDS2A(xa0, xa1, xr0 + off);
                LDS2A(xb0, xb1, xr1 + off);
#pragma unroll
                for (int j = 0; j < 8; j++) {
                    ull w0_, w1_;
                    LDS2A(w0_, w1_, s1a + (s0 + 8*j) * 272 + k * 16);
                    FMA2(sa[j],     xa0, w0_); FMA2(sa[j],     xa1, w1_);
                    FMA2(sa[8 + j], xb0, w0_); FMA2(sa[8 + j], xb1, w1_);
                }
            }
            bool v0 = i2 < n, v1 = (i2 + 32) < n;
#pragma unroll
            for (int j = 0; j < 8; j++) {
                int s = s0 + 8 * j;
                float2 f0 = unpk(sa[j]);
                float2 f1 = unpk(sa[8 + j]);
                sc[s * 68 + i2]      = v0 ? __expf(f0.x + f0.y) : 0.f;
                sc[s * 68 + i2 + 32] = v1 ? __expf(f1.x + f1.y) : 0.f;
            }
        }
        __syncthreads();
#pragma unroll 2
        for (int i = 0; i < 64; i++) {
            uint32_t a = xsA + i * 272 + xg;
            ull x0, x1, x2, x3;
            LDS2A(x0, x1, a);
            LDS2A(x2, x3, a + 16);
            float w0 = sc[sp * 68 + i];
            float w1 = sc[(sp + 32) * 68 + i];
            zs0 += w0; zs1 += w1;
            ull m2;
            m2 = pack2(w0, w0);
            FMA2(acc[0], m2, x0); FMA2(acc[1], m2, x1);
            FMA2(acc[2], m2, x2); FMA2(acc[3], m2, x3);
            m2 = pack2(w1, w1);
            FMA2(acc[4], m2, x0); FMA2(acc[5], m2, x1);
            FMA2(acc[6], m2, x2); FMA2(acc[7], m2, x3);
        }
    }
    float* pv = g_partV + (size_t)blockIdx.x * 4096;
#pragma unroll
    for (int q = 0; q < 2; q++) {
        int s = sp + 32 * q;
        int d = g * 8;
        float2 a0 = unpk(acc[4*q]),   a1 = unpk(acc[4*q+1]);
        float2 a2 = unpk(acc[4*q+2]), a3 = unpk(acc[4*q+3]);
        pv[s*64 + d]   = a0.x; pv[s*64 + d+1] = a0.y;
        pv[s*64 + d+2] = a1.x; pv[s*64 + d+3] = a1.y;
        pv[s*64 + d+4] = a2.x; pv[s*64 + d+5] = a2.y;
        pv[s*64 + d+6] = a3.x; pv[s*64 + d+7] = a3.y;
    }
    if (g == 0) {
        float* pz = g_partZ + blockIdx.x * 64;
        pz[sp] = zs0; pz[sp + 32] = zs1;
    }
}

// ---------------- Reductions ----------------
template<int PH>
__global__ void __launch_bounds__(256) kRed()
{
    const float* pU = (PH == 0) ? g_partU : g_partV;
    const float* pC = (PH == 0) ? g_partC : g_partZ;
    float* out = (PH == 0) ? g_sec1 : g_sec2;
    __shared__ float su[4][64];
    __shared__ float scv[4][64];
    int tid = threadIdx.x;
    int l = tid & 63, r = tid >> 6;
    int oid = blockIdx.x * 64 + l;
    int s = oid >> 6;
    float u = 0.f, c = 0.f;
    int b0 = r * (GR / 4);
#pragma unroll 4
    for (int b = b0; b < b0 + GR/4; b++) {
        u += pU[(size_t)b * 4096 + oid];
        c += pC[b * 64 + s];
    }
    su[r][l] = u; scv[r][l] = c;
    __syncthreads();
    if (r == 0) {
        u = su[0][l] + su[1][l] + su[2][l] + su[3][l];
        c = scv[0][l] + scv[1][l] + scv[2][l] + scv[3][l];
        out[oid] = u / c;
    }
}

// ---------------- kPre: fold weight chain into S1, S2, b1, b2 ----------------
__global__ void __launch_bounds__(256) kPre(
    const float* __restrict__ Went, const float* __restrict__ bent,
    const float* __restrict__ Wsi,  const float* __restrict__ bsi,
    const float* __restrict__ Wso,  const float* __restrict__ bso,
    const float* __restrict__ Wout, const float* __restrict__ bout)
{
    __shared__ float sA[4096];
    __shared__ float sB[4096];
    __shared__ float sM[4096];
    __shared__ float bv[64];
    int tid = threadIdx.x;
    for (int o = tid; o < 4096; o += 256) {
        sA[o] = g_sec2[o];
        sB[(o & 63) * 64 + (o >> 6)] = Went[o];
    }
    __syncthreads();
    for (int o = tid; o < 4096; o += 256) {
        int i = o >> 6, j = o & 63;
        float acc = 0.f;
        for (int k = 0; k < 64; k++) acc += sA[(i<<6)+k] * sB[(k<<6)+j];
        sM[o] = acc;
    }
    __syncthreads();
    for (int o = tid; o < 4096; o += 256) sB[(o & 63) * 64 + (o >> 6)] = Wso[o];
    __syncthreads();
    for (int o = tid; o < 4096; o += 256) {
        int i = o >> 6, j = o & 63;
        float acc = 0.f;
        for (int k = 0; k < 64; k++) acc += sM[(i<<6)+k] * sB[(k<<6)+j];
        g_S1[o] = acc;
    }
    if (tid < 64) {
        float acc = bso[tid];
        for (int k = 0; k < 64; k++) acc += sB[(k<<6)+tid] * bent[k];
        g_b1[tid] = acc;
    }
    __syncthreads();
    for (int o = tid; o < 4096; o += 256) sB[(o & 63) * 64 + (o >> 6)] = Wsi[o];
    __syncthreads();
    for (int o = tid; o < 4096; o += 256) {
        int i = o >> 6, j = o & 63;
        float acc = 0.f;
        for (int k = 0; k < 64; k++) acc += sM[(i<<6)+k] * sB[(k<<6)+j];
        sA[o] = acc;
    }
    if (tid < 64) {
        float acc = bsi[tid];
        for (int k = 0; k < 64; k++) acc += sB[(k<<6)+tid] * bent[k];
        bv[tid] = acc;
    }
    __syncthreads();
    for (int o = tid; o < 4096; o += 256) sB[(o & 63) * 64 + (o >> 6)] = Wout[o];
    __syncthreads();
    for (int o = tid; o < 4096; o += 256) {
        int i = o >> 6, j = o & 63;
        float acc = 0.f;
        for (int k = 0; k < 64; k++) acc += sA[(i<<6)+k] * sB[(k<<6)+j];
        g_S2[o] = acc;
    }
    if (tid < 64) {
        float acc = bout[tid];
        for (int k = 0; k < 64; k++) acc += sB[(k<<6)+tid] * bv[k];
        g_b2[tid] = acc;
    }
}

// ---------------- Phase C: d-split, 512 threads = (256 entities x 2 halves), 2 blocks/SM ----------------
// thread = (e = tid&255, h = tid>>8); computes outputs d in [32h, 32h+32).
// smem floats: bufW 4352, bias 128, zbuf 512, scratch 64*262
#define CT 512
#define EPB 256
#define SCRS 262
#define BW_STRIDE 68
#define SMC_FLOATS (4352 + 128 + 512 + 64*SCRS)
#define SMC_BYTES  (SMC_FLOATS * 4)

__global__ void __launch_bounds__(CT, 2) kC(
    const float* __restrict__ x,
    const float* __restrict__ Wout,
    float* __restrict__ out1, float* __restrict__ out2)
{
    extern __shared__ __align__(16) float sm[];
    float* bufW = sm;               // [k or s][64] stride 68
    float* bias = sm + 4352;        // b1(64), b2(64)
    float* zbuf = sm + 4480;        // [2][256] partial softmax sums
    float* scratch = sm + 4992;     // [64][SCRS]

    int tid = threadIdx.x;
    int e = tid & 255, h = tid >> 8;
    if (tid < 64) { bias[tid] = g_b1[tid]; bias[tid + 64] = g_b2[tid]; }

    const size_t fMax = (size_t)EN * 64;
    size_t fBase = (size_t)blockIdx.x * (EPB * 64);
    for (int vi = tid; vi < EPB*64; vi += CT) {
        size_t f = fBase + vi;
        float val = (f < fMax) ? x[f] : 0.f;
        scratch[(vi & 63) * SCRS + (vi >> 6)] = val;
    }

    uint32_t aBufW = sptr(bufW);
    uint32_t aScr  = sptr(scratch);
    uint32_t sc0   = aScr + e * 4;
    uint32_t wOff  = h * 128;        // byte offset of this thread's half-row

#define LOADW_T(SRC) do{ __syncthreads(); \
    for (int o = tid; o < 4096; o += CT) bufW[(o & 63)*BW_STRIDE + (o >> 6)] = (SRC)[o]; \
    __syncthreads(); }while(0)
#define LOADW_N(SRC) do{ __syncthreads(); \
    for (int o = tid; o < 4096; o += CT) bufW[(o >> 6)*BW_STRIDE + (o & 63)] = (SRC)[o]; \
    __syncthreads(); }while(0)

// one pass over k: scalar = scratch[k][e] * SCALE; half-row FMA
#define STAGEH(A, SCALE) do{ \
    _Pragma("unroll 2") \
    for (int k = 0; k < 64; k++) { \
        float xv_; LDSF(xv_, sc0 + k * (SCRS*4)); \
        float s_ = xv_ * (SCALE); \
        ull m2 = pack2(s_, s_); \
        uint32_t rb = aBufW + k * (BW_STRIDE*4) + wOff; \
        ROWH(A, rb); \
    } }while(0)

    ull a0[16];

    // ---- stage t: t[s] (s in this thread's half) = x . sec2[s] ----
    LOADW_T(g_sec2);
#pragma unroll
    for (int i = 0; i < 16; i++) a0[i] = 0ull;
    STAGEH(a0, 1.0f);

    // ---- split softmax: exp -> scratch (praw), partial Z -> zbuf ----
    __syncthreads();                 // everyone done reading x
    {
        float Z = 0.f;
#pragma unroll
        for (int i = 0; i < 16; i++) {
            float2 f = unpk(a0[i]);
            float p0 = __expf(f.x), p1 = __expf(f.y);
            Z += p0 + p1;
            int s = 32 * h + 2 * i;
            STSF(aScr + (s * SCRS + e) * 4, p0);
            STSF(aScr + ((s + 1) * SCRS + e) * 4, p1);
        }
        zbuf[h * 256 + e] = Z;
    }
    __syncthreads();
    float invZ = 1.f / (zbuf[e] + zbuf[256 + e]);

    size_t eg = (size_t)blockIdx.x * EPB + e;
    bool live = eg < EN;

    // ---- stage o1: leaky(p @ S1 + b1)[d-half] -> out1 (float4) ----
    LOADW_N(g_S1);
#pragma unroll
    for (int i = 0; i < 16; i++)
        a0[i] = pack2(bias[32*h + 2*i], bias[32*h + 2*i + 1]);
    STAGEH(a0, invZ);
    if (live) {
        float4* p0 = (float4*)(out1 + eg * 64 + 32 * h);
#pragma unroll
        for (int i = 0; i < 8; i++) {
            float2 fa = unpk(a0[2*i]), fb = unpk(a0[2*i+1]);
            float4 v;
            v.x = fa.x >= 0.f ? fa.x : 0.01f * fa.x;
            v.y = fa.y >= 0.f ? fa.y : 0.01f * fa.y;
            v.z = fb.x >= 0.f ? fb.x : 0.01f * fb.x;
            v.w = fb.y >= 0.f ? fb.y : 0.01f * fb.y;
            p0[i] = v;
        }
    }

    // ---- stage S2: acc = (p @ S2 + b2)[d-half] (kept in regs) ----
    LOADW_N(g_S2);
#pragma unroll
    for (int i = 0; i < 16; i++)
        a0[i] = pack2(bias[64 + 32*h + 2*i], bias[64 + 32*h + 2*i + 1]);
    STAGEH(a0, invZ);

    // ---- restage x, then acc += (x @ Wout^T)[d-half] ----
    __syncthreads();                 // everyone done reading praw
    for (int vi = tid; vi < EPB*64; vi += CT) {
        size_t f = fBase + vi;
        float val = (f < fMax) ? x[f] : 0.f;
        scratch[(vi & 63) * SCRS + (vi >> 6)] = val;
    }
    LOADW_T(Wout);
    STAGEH(a0, 1.0f);

    // ---- o2: leaky, stage into scratch (x dead), coalesced store ----
    __syncthreads();
#pragma unroll
    for (int i = 0; i < 16; i++) {
        float2 f = unpk(a0[i]);
        f.x = f.x >= 0.f ? f.x : 0.01f * f.x;
        f.y = f.y >= 0.f ? f.y : 0.01f * f.y;
        int s = 32 * h + 2 * i;
        STSF(aScr + (s * SCRS + e) * 4, f.x);
        STSF(aScr + ((s + 1) * SCRS + e) * 4, f.y);
    }
    __syncthreads();
    for (int vi = tid; vi < EPB*64; vi += CT) {
        size_t f = fBase + vi;
        if (f < fMax) out2[f] = scratch[(vi & 63) * SCRS + (vi >> 6)];
    }
}

extern "C" void kernel_launch(void* const* d_in, const int* in_sizes, int n_in,
                              void* d_out, int out_size)
{
    const float* x    = (const float*)d_in[0];
    const float* w    = (const float*)d_in[1];
    const float* Went = (const float*)d_in[2];
    const float* bent = (const float*)d_in[3];
    const float* Wsi  = (const float*)d_in[4];
    const float* bsi  = (const float*)d_in[5];
    const float* Wso  = (const float*)d_in[6];
    const float* bso  = (const float*)d_in[7];
    const float* Wout = (const float*)d_in[8];
    const float* bout = (const float*)d_in[9];

    float* out1 = (float*)d_out;
    float* out2 = out1 + (size_t)EN * 64;

    cudaFuncSetAttribute(kB, cudaFuncAttributeMaxDynamicSharedMemorySize, KB_BYTES);
    cudaFuncSetAttribute(kC, cudaFuncAttributeMaxDynamicSharedMemorySize, SMC_BYTES);

    kNop<<<1, 32>>>();
    kNop<<<1, 32>>>();
    kNop<<<1, 32>>>();
    kA<<<GR, 128>>>(x, w);
    kRed<0><<<64, 256>>>();
    kB<<<GR, 256, KB_BYTES>>>(x);
    kRed<1><<<64, 256>>>();
    kPre<<<1, 256>>>(Went, bent, Wsi, bsi, Wso, bso, Wout, bout);
    int gridC = (EN + EPB - 1) / EPB;
    kC<<<gridC, CT, SMC_BYTES>>>(x, Wout, out1, out2);
}

// round 16
// speedup vs baseline: 1.3223x; 1.1978x over previous
#include <cuda_runtime.h>
#include <math.h>
#include <stdint.h>

#define EN 500000
#define GR 888            // 6 * 148 SMs
#define PERB 564          // ceil(EN/GR)

typedef unsigned long long ull;

__device__ float g_partU[(size_t)GR*4096];
__device__ float g_partC[GR*64];
__device__ float g_partV[(size_t)GR*4096];
__device__ float g_partZ[GR*64];
__device__ float g_sec1[4096];
__device__ float g_sec2[4096];
__device__ float g_S1[4096];     // sec2 @ Went^T @ Wso^T
__device__ float g_S2[4096];     // sec2 @ Went^T @ Wsi^T @ Wout^T
__device__ float g_b1[64];
__device__ float g_b2[64];

__device__ __forceinline__ ull pack2(float x, float y){
    ull r; asm("mov.b64 %0,{%1,%2};" : "=l"(r) : "f"(x), "f"(y)); return r;
}
__device__ __forceinline__ float2 unpk(ull v){
    float2 r; asm("mov.b64 {%0,%1},%2;" : "=f"(r.x), "=f"(r.y) : "l"(v)); return r;
}
__device__ __forceinline__ uint32_t sptr(const void* p){
    return (uint32_t)__cvta_generic_to_shared(p);
}
#define FMA2(d,a,b) asm("fma.rn.f32x2 %0,%1,%2,%0;" : "+l"(d) : "l"(a), "l"(b))
#define LDS2(a,b,base,OFF) asm volatile("ld.shared.v2.u64 {%0,%1},[%2+" #OFF "];" : "=l"(a), "=l"(b) : "r"(base))
#define LDS2A(a,b,addr) asm volatile("ld.shared.v2.u64 {%0,%1},[%2];" : "=l"(a), "=l"(b) : "r"(addr))
#define LDS64(v,addr) asm volatile("ld.shared.b64 %0,[%1];" : "=l"(v) : "r"(addr))
#define STS64(addr,v) asm volatile("st.shared.b64 [%0],%1;" :: "r"(addr), "l"(v) : "memory")

// 2-entity pair FMA: 16B of weights feeds both entities' accumulators (kC)
#define PAIR2(A0,A1,B0,B1,RB,OFF) do{ ull w0_,w1_; LDS2(w0_,w1_,RB,OFF); \
  FMA2(A0,m2a,w0_); FMA2(A1,m2a,w1_); FMA2(B0,m2b,w0_); FMA2(B1,m2b,w1_);}while(0)
#define ROW2(A,B,RB) do{ \
  PAIR2(A[0],A[1],B[0],B[1],RB,0);     PAIR2(A[2],A[3],B[2],B[3],RB,16); \
  PAIR2(A[4],A[5],B[4],B[5],RB,32);    PAIR2(A[6],A[7],B[6],B[7],RB,48); \
  PAIR2(A[8],A[9],B[8],B[9],RB,64);    PAIR2(A[10],A[11],B[10],B[11],RB,80); \
  PAIR2(A[12],A[13],B[12],B[13],RB,96);  PAIR2(A[14],A[15],B[14],B[15],RB,112); \
  PAIR2(A[16],A[17],B[16],B[17],RB,128); PAIR2(A[18],A[19],B[18],B[19],RB,144); \
  PAIR2(A[20],A[21],B[20],B[21],RB,160); PAIR2(A[22],A[23],B[22],B[23],RB,176); \
  PAIR2(A[24],A[25],B[24],B[25],RB,192); PAIR2(A[26],A[27],B[26],B[27],RB,208); \
  PAIR2(A[28],A[29],B[28],B[29],RB,224); PAIR2(A[30],A[31],B[30],B[31],RB,240);}while(0)

__global__ void kNop() {}

// Swizzled row: 272 B; 32B chunk g at byte g*32 + (g>>2)*16; 16B chunk k at k*16 + (k>>3)*16.

// ---------------- Phase A: 128 threads = 16 sp x 8 g; 4 sectors/thread ----------------
__global__ void __launch_bounds__(128) kA(const float* __restrict__ x,
                                          const float* __restrict__ w)
{
    __shared__ __align__(16) float xs[32 * 68];
    __shared__ __align__(16) float ws[2048];
    const float4* x4 = (const float4*)x;
    const float4* w4 = (const float4*)w;
    float4* xs4 = (float4*)xs;
    float4* ws4 = (float4*)ws;
    int tid = threadIdx.x;
    int sp = tid >> 3, g = tid & 7;
    uint32_t xsA = sptr(xs);
    uint32_t xg = g * 32 + (g >> 2) * 16;

    ull acc[16];
#pragma unroll
    for (int i = 0; i < 16; i++) acc[i] = 0ull;
    float cs0 = 0.f, cs1 = 0.f, cs2 = 0.f, cs3 = 0.f;
    int e0 = blockIdx.x * PERB;
    int e1 = e0 + PERB; if (e1 > EN) e1 = EN;

    for (int base = e0; base < e1; base += 32) {
        int n = e1 - base; if (n > 32) n = 32;
        __syncthreads();
        for (int vi = tid; vi < 512; vi += 128) {
            int el = vi >> 4, j = vi & 15;
            float4 xv = make_float4(0.f,0.f,0.f,0.f);
            float4 wv = xv;
            if (el < n) {
                size_t o = (size_t)(base + el) * 16 + j;
                xv = x4[o]; wv = w4[o];
            }
            xs4[el * 17 + j + (j >> 3)] = xv;   // swizzled
            ws4[el * 16 + j] = wv;
        }
        __syncthreads();
#pragma unroll 4
        for (int i = 0; i < 32; i++) {
            float w0 = ws[(i << 6) + sp];
            float w1 = ws[(i << 6) + sp + 16];
            float w2 = ws[(i << 6) + sp + 32];
            float w3 = ws[(i << 6) + sp + 48];
            cs0 += w0; cs1 += w1; cs2 += w2; cs3 += w3;
            uint32_t a = xsA + i * 272 + xg;
            ull x0, x1, x2, x3;
            LDS2A(x0, x1, a);
            LDS2A(x2, x3, a + 16);
            ull m2a, m2b;
            m2a = pack2(w0, w0);
            FMA2(acc[0], m2a, x0); FMA2(acc[1], m2a, x1);
            FMA2(acc[2], m2a, x2); FMA2(acc[3], m2a, x3);
            m2b = pack2(w1, w1);
            FMA2(acc[4], m2b, x0); FMA2(acc[5], m2b, x1);
            FMA2(acc[6], m2b, x2); FMA2(acc[7], m2b, x3);
            m2a = pack2(w2, w2);
            FMA2(acc[8], m2a, x0); FMA2(acc[9], m2a, x1);
            FMA2(acc[10], m2a, x2); FMA2(acc[11], m2a, x3);
            m2b = pack2(w3, w3);
            FMA2(acc[12], m2b, x0); FMA2(acc[13], m2b, x1);
            FMA2(acc[14], m2b, x2); FMA2(acc[15], m2b, x3);
        }
    }
    float* pu = g_partU + (size_t)blockIdx.x * 4096;
#pragma unroll
    for (int t = 0; t < 4; t++) {
        int sector = sp + 16 * t;
        int d = g * 8;
        float2 a0 = unpk(acc[4*t]),   a1 = unpk(acc[4*t+1]);
        float2 a2 = unpk(acc[4*t+2]), a3 = unpk(acc[4*t+3]);
        pu[sector*64 + d]   = a0.x; pu[sector*64 + d+1] = a0.y;
        pu[sector*64 + d+2] = a1.x; pu[sector*64 + d+3] = a1.y;
        pu[sector*64 + d+4] = a2.x; pu[sector*64 + d+5] = a2.y;
        pu[sector*64 + d+6] = a3.x; pu[sector*64 + d+7] = a3.y;
    }
    if (g == 0) {
        g_partC[blockIdx.x * 64 + sp]      = cs0;
        g_partC[blockIdx.x * 64 + sp + 16] = cs1;
        g_partC[blockIdx.x * 64 + sp + 32] = cs2;
        g_partC[blockIdx.x * 64 + sp + 48] = cs3;
    }
}

// ---------------- Phase B: 64-entity tiles, dynamic smem, 2 blocks/SM ----------------
#define KB_FLOATS (3 * 64 * 68)
#define KB_BYTES  (KB_FLOATS * 4)

__global__ void __launch_bounds__(256, 2) kB(const float* __restrict__ x)
{
    extern __shared__ __align__(16) float smb[];
    float* s1s = smb;
    float* xs  = smb + 4352;
    float* sc  = smb + 8704;          // [s][e] stride 68
    int tid = threadIdx.x;
    for (int o = tid; o < 4096; o += 256)
        s1s[(o >> 6) * 68 + (o & 63)] = g_sec1[o];

    const float4* x4 = (const float4*)x;
    float4* xs4 = (float4*)xs;
    int i2 = tid >> 3, s0 = tid & 7;
    int sp = tid >> 3, g = tid & 7;
    uint32_t xsA = sptr(xs);
    uint32_t s1a = sptr(s1s);
    uint32_t xg = g * 32 + (g >> 2) * 16;

    ull acc[8];
#pragma unroll
    for (int i = 0; i < 8; i++) acc[i] = 0ull;
    float zs0 = 0.f, zs1 = 0.f;

    int e0 = blockIdx.x * PERB;
    int e1 = e0 + PERB; if (e1 > EN) e1 = EN;

    for (int base = e0; base < e1; base += 64) {
        int n = e1 - base; if (n > 64) n = 64;
        __syncthreads();
        for (int vi = tid; vi < 1024; vi += 256) {
            int el = vi >> 4, j = vi & 15;
            float4 xv = make_float4(0.f,0.f,0.f,0.f);
            if (el < n) xv = x4[(size_t)(base + el) * 16 + j];
            xs4[el * 17 + j + (j >> 3)] = xv;   // swizzled
        }
        __syncthreads();
        {
            ull sa[16];
#pragma unroll
            for (int i = 0; i < 16; i++) sa[i] = 0ull;
            uint32_t xr0 = xsA + i2 * 272;
            uint32_t xr1 = xr0 + 32 * 272;
#pragma unroll
            for (int k = 0; k < 16; k++) {
                int off = k * 16 + (k >> 3) * 16;
                ull xa0, xa1, xb0, xb1;
                LDS2A(xa0, xa1, xr0 + off);
                LDS2A(xb0, xb1, xr1 + off);
#pragma unroll
                for (int j = 0; j < 8; j++) {
                    ull w0_, w1_;
                    LDS2A(w0_, w1_, s1a + (s0 + 8*j) * 272 + k * 16);
                    FMA2(sa[j],     xa0, w0_); FMA2(sa[j],     xa1, w1_);
                    FMA2(sa[8 + j], xb0, w0_); FMA2(sa[8 + j], xb1, w1_);
                }
            }
            bool v0 = i2 < n, v1 = (i2 + 32) < n;
#pragma unroll
            for (int j = 0; j < 8; j++) {
                int s = s0 + 8 * j;
                float2 f0 = unpk(sa[j]);
                float2 f1 = unpk(sa[8 + j]);
                sc[s * 68 + i2]      = v0 ? __expf(f0.x + f0.y) : 0.f;
                sc[s * 68 + i2 + 32] = v1 ? __expf(f1.x + f1.y) : 0.f;
            }
        }
        __syncthreads();
#pragma unroll 2
        for (int i = 0; i < 64; i++) {
            uint32_t a = xsA + i * 272 + xg;
            ull x0, x1, x2, x3;
            LDS2A(x0, x1, a);
            LDS2A(x2, x3, a + 16);
            float w0 = sc[sp * 68 + i];
            float w1 = sc[(sp + 32) * 68 + i];
            zs0 += w0; zs1 += w1;
            ull m2;
            m2 = pack2(w0, w0);
            FMA2(acc[0], m2, x0); FMA2(acc[1], m2, x1);
            FMA2(acc[2], m2, x2); FMA2(acc[3], m2, x3);
            m2 = pack2(w1, w1);
            FMA2(acc[4], m2, x0); FMA2(acc[5], m2, x1);
            FMA2(acc[6], m2, x2); FMA2(acc[7], m2, x3);
        }
    }
    float* pv = g_partV + (size_t)blockIdx.x * 4096;
#pragma unroll
    for (int q = 0; q < 2; q++) {
        int s = sp + 32 * q;
        int d = g * 8;
        float2 a0 = unpk(acc[4*q]),   a1 = unpk(acc[4*q+1]);
        float2 a2 = unpk(acc[4*q+2]), a3 = unpk(acc[4*q+3]);
        pv[s*64 + d]   = a0.x; pv[s*64 + d+1] = a0.y;
        pv[s*64 + d+2] = a1.x; pv[s*64 + d+3] = a1.y;
        pv[s*64 + d+4] = a2.x; pv[s*64 + d+5] = a2.y;
        pv[s*64 + d+6] = a3.x; pv[s*64 + d+7] = a3.y;
    }
    if (g == 0) {
        float* pz = g_partZ + blockIdx.x * 64;
        pz[sp] = zs0; pz[sp + 32] = zs1;
    }
}

// ---------------- Reductions ----------------
template<int PH>
__global__ void __launch_bounds__(256) kRed()
{
    const float* pU = (PH == 0) ? g_partU : g_partV;
    const float* pC = (PH == 0) ? g_partC : g_partZ;
    float* out = (PH == 0) ? g_sec1 : g_sec2;
    __shared__ float su[4][64];
    __shared__ float scv[4][64];
    int tid = threadIdx.x;
    int l = tid & 63, r = tid >> 6;
    int oid = blockIdx.x * 64 + l;
    int s = oid >> 6;
    float u = 0.f, c = 0.f;
    int b0 = r * (GR / 4);
#pragma unroll 4
    for (int b = b0; b < b0 + GR/4; b++) {
        u += pU[(size_t)b * 4096 + oid];
        c += pC[b * 64 + s];
    }
    su[r][l] = u; scv[r][l] = c;
    __syncthreads();
    if (r == 0) {
        u = su[0][l] + su[1][l] + su[2][l] + su[3][l];
        c = scv[0][l] + scv[1][l] + scv[2][l] + scv[3][l];
        out[oid] = u / c;
    }
}

// ---------------- kPre: fold weight chain into S1, S2, b1, b2 ----------------
__global__ void __launch_bounds__(256) kPre(
    const float* __restrict__ Went, const float* __restrict__ bent,
    const float* __restrict__ Wsi,  const float* __restrict__ bsi,
    const float* __restrict__ Wso,  const float* __restrict__ bso,
    const float* __restrict__ Wout, const float* __restrict__ bout)
{
    __shared__ float sA[4096];
    __shared__ float sB[4096];
    __shared__ float sM[4096];
    __shared__ float bv[64];
    int tid = threadIdx.x;
    for (int o = tid; o < 4096; o += 256) {
        sA[o] = g_sec2[o];
        sB[(o & 63) * 64 + (o >> 6)] = Went[o];
    }
    __syncthreads();
    for (int o = tid; o < 4096; o += 256) {
        int i = o >> 6, j = o & 63;
        float acc = 0.f;
        for (int k = 0; k < 64; k++) acc += sA[(i<<6)+k] * sB[(k<<6)+j];
        sM[o] = acc;
    }
    __syncthreads();
    for (int o = tid; o < 4096; o += 256) sB[(o & 63) * 64 + (o >> 6)] = Wso[o];
    __syncthreads();
    for (int o = tid; o < 4096; o += 256) {
        int i = o >> 6, j = o & 63;
        float acc = 0.f;
        for (int k = 0; k < 64; k++) acc += sM[(i<<6)+k] * sB[(k<<6)+j];
        g_S1[o] = acc;
    }
    if (tid < 64) {
        float acc = bso[tid];
        for (int k = 0; k < 64; k++) acc += sB[(k<<6)+tid] * bent[k];
        g_b1[tid] = acc;
    }
    __syncthreads();
    for (int o = tid; o < 4096; o += 256) sB[(o & 63) * 64 + (o >> 6)] = Wsi[o];
    __syncthreads();
    for (int o = tid; o < 4096; o += 256) {
        int i = o >> 6, j = o & 63;
        float acc = 0.f;
        for (int k = 0; k < 64; k++) acc += sM[(i<<6)+k] * sB[(k<<6)+j];
        sA[o] = acc;
    }
    if (tid < 64) {
        float acc = bsi[tid];
        for (int k = 0; k < 64; k++) acc += sB[(k<<6)+tid] * bent[k];
        bv[tid] = acc;
    }
    __syncthreads();
    for (int o = tid; o < 4096; o += 256) sB[(o & 63) * 64 + (o >> 6)] = Wout[o];
    __syncthreads();
    for (int o = tid; o < 4096; o += 256) {
        int i = o >> 6, j = o & 63;
        float acc = 0.f;
        for (int k = 0; k < 64; k++) acc += sA[(i<<6)+k] * sB[(k<<6)+j];
        g_S2[o] = acc;
    }
    if (tid < 64) {
        float acc = bout[tid];
        for (int k = 0; k < 64; k++) acc += sB[(k<<6)+tid] * bv[k];
        g_b2[tid] = acc;
    }
}

// ---------------- Phase C: R12 dataflow, half-size blocks -> 2 blocks/SM ----------------
// 128 threads, 256 entities/block (2 per thread, pair-interleaved scratch).
// SCRS must hold 256 entity columns: 258 (even -> b64 aligned).
#define CT 128
#define EPB 256
#define SCRS 258
#define BW_STRIDE 68
#define SMC_FLOATS (64*BW_STRIDE + 256 + 64*SCRS)
#define SMC_BYTES  (SMC_FLOATS * 4)

__global__ void __launch_bounds__(CT, 2) kC(
    const float* __restrict__ x,
    const float* __restrict__ Wout,
    float* __restrict__ out1, float* __restrict__ out2)
{
    extern __shared__ __align__(16) float sm[];
    float* bufW = sm;
    float* bias = sm + 64*BW_STRIDE;
    float* scratch = bias + 256;

    int tid = threadIdx.x;
    if (tid < 64) {
        bias[tid]      = g_b1[tid];
        bias[tid + 64] = g_b2[tid];
    }

    const size_t fMax = (size_t)EN * 64;
    size_t fBase = (size_t)blockIdx.x * (EPB * 64);
    for (int vi = tid; vi < EPB*64; vi += CT) {
        size_t f = fBase + vi;
        float val = (f < fMax) ? x[f] : 0.f;
        scratch[(vi & 63) * SCRS + (vi >> 6)] = val;
    }

    uint32_t aBufW = sptr(bufW);
    uint32_t aScr  = sptr(scratch);
    uint32_t sc0   = aScr + tid * 8;

#define LOADW_T(SRC) do{ __syncthreads(); \
    for (int o = tid; o < 4096; o += CT) bufW[(o & 63)*BW_STRIDE + (o >> 6)] = (SRC)[o]; \
    __syncthreads(); }while(0)
#define LOADW_N(SRC) do{ __syncthreads(); \
    for (int o = tid; o < 4096; o += CT) bufW[(o >> 6)*BW_STRIDE + (o & 63)] = (SRC)[o]; \
    __syncthreads(); }while(0)

#define STAGE(A0,A1) do{ \
    _Pragma("unroll 2") \
    for (int k = 0; k < 64; k++) { \
        ull xv_; LDS64(xv_, sc0 + k * (SCRS*4)); \
        float2 fx_ = unpk(xv_); \
        ull m2a = pack2(fx_.x, fx_.x); \
        ull m2b = pack2(fx_.y, fx_.y); \
        uint32_t rb = aBufW + k * (BW_STRIDE*4); \
        ROW2(A0, A1, rb); \
    } }while(0)

    ull a0[32], a1[32];

    // ---- stage t: t = x . sec2^T ----
    LOADW_T(g_sec2);
#pragma unroll
    for (int i = 0; i < 32; i++) { a0[i] = 0ull; a1[i] = 0ull; }
    STAGE(a0, a1);
    {
        float Z0 = 0.f, Z1 = 0.f;
#pragma unroll
        for (int i = 0; i < 32; i++) {
            float2 f0 = unpk(a0[i]);
            f0.x = __expf(f0.x); f0.y = __expf(f0.y);
            Z0 += f0.x + f0.y;
            a0[i] = pack2(f0.x, f0.y);
            float2 f1 = unpk(a1[i]);
            f1.x = __expf(f1.x); f1.y = __expf(f1.y);
            Z1 += f1.x + f1.y;
            a1[i] = pack2(f1.x, f1.y);
        }
        float i0 = 1.f / Z0, i1 = 1.f / Z1;
#pragma unroll
        for (int i = 0; i < 32; i++) {
            float2 f0 = unpk(a0[i]);
            float2 f1 = unpk(a1[i]);
            STS64(sc0 + (2*i)   * (SCRS*4), pack2(f0.x * i0, f1.x * i1));
            STS64(sc0 + (2*i+1) * (SCRS*4), pack2(f0.y * i0, f1.y * i1));
        }
    }

    size_t ebase = (size_t)blockIdx.x * EPB + 2 * tid;
    bool live0 = ebase < EN, live1 = ebase + 1 < EN;

    // ---- stage o1: leaky(p @ S1 + b1) -> out1 (float4 stores; p stays in scratch) ----
    LOADW_N(g_S1);
#pragma unroll
    for (int i = 0; i < 32; i++) {
        ull bvv = pack2(bias[2*i], bias[2*i+1]);
        a0[i] = bvv; a1[i] = bvv;
    }
    STAGE(a0, a1);
    {
        float4* p0 = (float4*)(out1 + ebase * 64);
        float4* p1 = (float4*)(out1 + (ebase + 1) * 64);
#pragma unroll
        for (int i = 0; i < 16; i++) {
            float2 fa = unpk(a0[2*i]), fb = unpk(a0[2*i+1]);
            float4 v0;
            v0.x = fa.x >= 0.f ? fa.x : 0.01f * fa.x;
            v0.y = fa.y >= 0.f ? fa.y : 0.01f * fa.y;
            v0.z = fb.x >= 0.f ? fb.x : 0.01f * fb.x;
            v0.w = fb.y >= 0.f ? fb.y : 0.01f * fb.y;
            if (live0) p0[i] = v0;
            float2 fc = unpk(a1[2*i]), fd = unpk(a1[2*i+1]);
            float4 v1;
            v1.x = fc.x >= 0.f ? fc.x : 0.01f * fc.x;
            v1.y = fc.y >= 0.f ? fc.y : 0.01f * fc.y;
            v1.z = fd.x >= 0.f ? fd.x : 0.01f * fd.x;
            v1.w = fd.y >= 0.f ? fd.y : 0.01f * fd.y;
            if (live1) p1[i] = v1;
        }
    }

    // ---- stage S2: acc = p @ S2 + b2 (kept in regs) ----
    LOADW_N(g_S2);
#pragma unroll
    for (int i = 0; i < 32; i++) {
        ull bvv = pack2(bias[64 + 2*i], bias[64 + 2*i+1]);
        a0[i] = bvv; a1[i] = bvv;
    }
    STAGE(a0, a1);

    // ---- restage x, then acc += x @ Wout^T ----
    __syncthreads();
    for (int vi = tid; vi < EPB*64; vi += CT) {
        size_t f = fBase + vi;
        float val = (f < fMax) ? x[f] : 0.f;
        scratch[(vi & 63) * SCRS + (vi >> 6)] = val;
    }
    LOADW_T(Wout);
    STAGE(a0, a1);

    // ---- o2: leaky, stage into scratch (x dead), coalesced store ----
    __syncthreads();
#pragma unroll
    for (int i = 0; i < 32; i++) {
        float2 f0 = unpk(a0[i]);
        f0.x = f0.x >= 0.f ? f0.x : 0.01f * f0.x;
        f0.y = f0.y >= 0.f ? f0.y : 0.01f * f0.y;
        float2 f1 = unpk(a1[i]);
        f1.x = f1.x >= 0.f ? f1.x : 0.01f * f1.x;
        f1.y = f1.y >= 0.f ? f1.y : 0.01f * f1.y;
        STS64(sc0 + (2*i)   * (SCRS*4), pack2(f0.x, f1.x));
        STS64(sc0 + (2*i+1) * (SCRS*4), pack2(f0.y, f1.y));
    }
    __syncthreads();
    for (int vi = tid; vi < EPB*64; vi += CT) {
        size_t f = fBase + vi;
        if (f < fMax) out2[f] = scratch[(vi & 63) * SCRS + (vi >> 6)];
    }
}

extern "C" void kernel_launch(void* const* d_in, const int* in_sizes, int n_in,
                              void* d_out, int out_size)
{
    const float* x    = (const float*)d_in[0];
    const float* w    = (const float*)d_in[1];
    const float* Went = (const float*)d_in[2];
    const float* bent = (const float*)d_in[3];
    const float* Wsi  = (const float*)d_in[4];
    const float* bsi  = (const float*)d_in[5];
    const float* Wso  = (const float*)d_in[6];
    const float* bso  = (const float*)d_in[7];
    const float* Wout = (const float*)d_in[8];
    const float* bout = (const float*)d_in[9];

    float* out1 = (float*)d_out;
    float* out2 = out1 + (size_t)EN * 64;

    cudaFuncSetAttribute(kB, cudaFuncAttributeMaxDynamicSharedMemorySize, KB_BYTES);
    cudaFuncSetAttribute(kC, cudaFuncAttributeMaxDynamicSharedMemorySize, SMC_BYTES);

    kNop<<<1, 32>>>();
    kNop<<<1, 32>>>();
    kNop<<<1, 32>>>();
    kA<<<GR, 128>>>(x, w);
    kRed<0><<<64, 256>>>();
    kB<<<GR, 256, KB_BYTES>>>(x);
    kRed<1><<<64, 256>>>();
    kPre<<<1, 256>>>(Went, bent, Wsi, bsi, Wso, bso, Wout, bout);
    int gridC = (EN + EPB - 1) / EPB;
    kC<<<gridC, CT, SMC_BYTES>>>(x, Wout, out1, out2);
}